// round 2
// baseline (speedup 1.0000x reference)
#include <cuda_runtime.h>
#include <cuda_bf16.h>
#include <cstdint>

// Problem constants (fixed by the dataset)
#define D_ATOM 256
#define D_EDGE 256
#define D_CAT  768          // 2*D_EDGE + D_ATOM
#define MAX_ATOMS 100000

// Scratch: concatenated x = [x1 | x2 | h], row-major, ld = 768.
// 100000 * 768 * 4B = 307.2 MB static device array (allocation-free rule).
__device__ float g_xcat[(size_t)MAX_ATOMS * D_CAT];

// ---------------------------------------------------------------------------
// Kernel 1: init scratch. Cols [0,512) = 0 (atomic targets), cols [512,768) = h.
// One thread per float4 of the scratch: 100000 * 192 threads.
// ---------------------------------------------------------------------------
__global__ void init_xcat_kernel(const float* __restrict__ h, int nAtoms) {
    size_t gid = (size_t)blockIdx.x * blockDim.x + threadIdx.x;
    size_t total = (size_t)nAtoms * (D_CAT / 4);
    if (gid >= total) return;
    int row = (int)(gid / (D_CAT / 4));
    int cv  = (int)(gid % (D_CAT / 4));   // float4 index within row, 0..191
    float4 v;
    if (cv < 128) {
        v = make_float4(0.f, 0.f, 0.f, 0.f);
    } else {
        v = *(const float4*)(h + (size_t)row * D_ATOM + (size_t)(cv - 128) * 4);
    }
    *(float4*)(g_xcat + (size_t)row * D_CAT + (size_t)cv * 4) = v;
}

// ---------------------------------------------------------------------------
// Kernel 2: scatter. 64 threads per edge (one float4 chunk of the 256-dim row
// each). Each thread does 4 vector reductions (red.global.add.v4.f32):
//   x1[id1] += m1chunk ; x1[id3] -= m1chunk ; x2[id2] += m2chunk ; x2[id4] -= m2chunk
// ---------------------------------------------------------------------------
__device__ __forceinline__ void red_add_v4(float* addr, float4 v) {
    asm volatile("red.global.add.v4.f32 [%0], {%1, %2, %3, %4};"
                 :: "l"(addr), "f"(v.x), "f"(v.y), "f"(v.z), "f"(v.w)
                 : "memory");
}

__global__ void scatter_kernel(const float* __restrict__ m1,
                               const float* __restrict__ m2,
                               const int* __restrict__ id1,
                               const int* __restrict__ id2,
                               const int* __restrict__ id3,
                               const int* __restrict__ id4,
                               int nEdges) {
    size_t gid = (size_t)blockIdx.x * blockDim.x + threadIdx.x;
    size_t total = (size_t)nEdges * 64;   // 64 float4 chunks per 256-dim row
    if (gid >= total) return;
    int e = (int)(gid >> 6);
    int c = (int)(gid & 63);

    float4 v1 = *(const float4*)(m1 + (size_t)e * D_EDGE + (size_t)c * 4);
    float4 v2 = *(const float4*)(m2 + (size_t)e * D_EDGE + (size_t)c * 4);
    float4 n1 = make_float4(-v1.x, -v1.y, -v1.z, -v1.w);
    float4 n2 = make_float4(-v2.x, -v2.y, -v2.z, -v2.w);

    int i1 = __ldg(id1 + e);
    int i2 = __ldg(id2 + e);
    int i3 = __ldg(id3 + e);
    int i4 = __ldg(id4 + e);

    size_t coff = (size_t)c * 4;
    red_add_v4(g_xcat + (size_t)i1 * D_CAT + coff,          v1);
    red_add_v4(g_xcat + (size_t)i3 * D_CAT + coff,          n1);
    red_add_v4(g_xcat + (size_t)i2 * D_CAT + D_EDGE + coff, v2);
    red_add_v4(g_xcat + (size_t)i4 * D_CAT + D_EDGE + coff, n2);
}

// ---------------------------------------------------------------------------
// Kernel 3: fp32 SGEMM  C[M,256] = Xcat[M,768] @ W[768,256]
// 128x128 tile, BK=16, 256 threads, 8x8 microtile per thread.
// (Known-slow fp32 path — baseline; will be replaced with tcgen05.)
// ---------------------------------------------------------------------------
#define BM 128
#define BN 128
#define BK 16

__global__ __launch_bounds__(256)
void gemm_kernel(const float* __restrict__ B,   // W: 768 x 256
                 float* __restrict__ C,         // out: M x 256
                 int M) {
    __shared__ float As[BK][BM];   // stored transposed: As[k][m]
    __shared__ float Bs[BK][BN];

    const int tid = threadIdx.x;
    const int tx = tid & 15;          // 0..15 (N direction)
    const int ty = tid >> 4;          // 0..15 (M direction)
    const int bm = blockIdx.y * BM;
    const int bn = blockIdx.x * BN;

    const float* A = g_xcat;

    float acc[8][8];
    #pragma unroll
    for (int i = 0; i < 8; i++)
        #pragma unroll
        for (int j = 0; j < 8; j++) acc[i][j] = 0.f;

    for (int k0 = 0; k0 < D_CAT; k0 += BK) {
        // Load A tile (128 x 16) as 512 float4, transposed into As[k][m]
        #pragma unroll
        for (int i = 0; i < 2; i++) {
            int idx = tid + i * 256;       // 0..511
            int row = idx >> 2;            // 0..127
            int cv  = idx & 3;             // 0..3
            float4 a = make_float4(0.f, 0.f, 0.f, 0.f);
            int gr = bm + row;
            if (gr < M)
                a = *(const float4*)(A + (size_t)gr * D_CAT + k0 + cv * 4);
            As[cv * 4 + 0][row] = a.x;
            As[cv * 4 + 1][row] = a.y;
            As[cv * 4 + 2][row] = a.z;
            As[cv * 4 + 3][row] = a.w;
        }
        // Load B tile (16 x 128) as 512 float4
        #pragma unroll
        for (int i = 0; i < 2; i++) {
            int idx = tid + i * 256;
            int row = idx >> 5;            // 0..15
            int cv  = idx & 31;            // 0..31
            float4 b = *(const float4*)(B + (size_t)(k0 + row) * 256 + bn + cv * 4);
            *(float4*)&Bs[row][cv * 4] = b;
        }
        __syncthreads();

        #pragma unroll
        for (int k = 0; k < BK; k++) {
            float ar[8], br[8];
            #pragma unroll
            for (int j = 0; j < 8; j++) ar[j] = As[k][ty * 8 + j];
            #pragma unroll
            for (int j = 0; j < 8; j++) br[j] = Bs[k][tx * 8 + j];
            #pragma unroll
            for (int i = 0; i < 8; i++)
                #pragma unroll
                for (int j = 0; j < 8; j++)
                    acc[i][j] += ar[i] * br[j];
        }
        __syncthreads();
    }

    // Store C
    #pragma unroll
    for (int i = 0; i < 8; i++) {
        int gr = bm + ty * 8 + i;
        if (gr < M) {
            float* cp = C + (size_t)gr * 256 + bn + tx * 8;
            *(float4*)(cp + 0) = make_float4(acc[i][0], acc[i][1], acc[i][2], acc[i][3]);
            *(float4*)(cp + 4) = make_float4(acc[i][4], acc[i][5], acc[i][6], acc[i][7]);
        }
    }
}

// ---------------------------------------------------------------------------
// Launch. Input order (metadata): h, m1, m2, id1, id2, id3, id4, W
// ---------------------------------------------------------------------------
extern "C" void kernel_launch(void* const* d_in, const int* in_sizes, int n_in,
                              void* d_out, int out_size) {
    const float* h  = (const float*)d_in[0];
    const float* m1 = (const float*)d_in[1];
    const float* m2 = (const float*)d_in[2];
    const int* id1  = (const int*)d_in[3];
    const int* id2  = (const int*)d_in[4];
    const int* id3  = (const int*)d_in[5];
    const int* id4  = (const int*)d_in[6];
    const float* W  = (const float*)d_in[7];
    float* out      = (float*)d_out;

    const int nAtoms = in_sizes[0] / D_ATOM;   // 100000
    const int nEdges = in_sizes[3];            // 800000

    // 1) init scratch: zero x-region, copy h into concat tail
    {
        size_t total = (size_t)nAtoms * (D_CAT / 4);
        int threads = 256;
        int blocks = (int)((total + threads - 1) / threads);
        init_xcat_kernel<<<blocks, threads>>>(h, nAtoms);
    }
    // 2) scatter edges
    {
        size_t total = (size_t)nEdges * 64;
        int threads = 256;
        int blocks = (int)((total + threads - 1) / threads);
        scatter_kernel<<<blocks, threads>>>(m1, m2, id1, id2, id3, id4, nEdges);
    }
    // 3) GEMM
    {
        dim3 grid(256 / BN, (nAtoms + BM - 1) / BM);  // (2, 782)
        gemm_kernel<<<grid, 256>>>(W, out, nAtoms);
    }
}

// round 4
// speedup vs baseline: 1.3375x; 1.3375x over previous
#include <cuda_runtime.h>
#include <cuda_bf16.h>
#include <cstdint>

// Problem constants (fixed by the dataset)
#define D_ATOM 256
#define D_EDGE 256
#define D_CAT  768          // 2*D_EDGE + D_ATOM
#define MAX_ATOMS 100000

// Scratch: concatenated x = [x1 | x2 | h], row-major, ld = 768. (307.2 MB)
__device__ float g_xcat[(size_t)MAX_ATOMS * D_CAT];
// W transposed + split into bf16 hi/lo: Wt[n][k] = W[k][n]
__device__ __nv_bfloat16 g_Wt_hi[256 * 768];
__device__ __nv_bfloat16 g_Wt_lo[256 * 768];

// ============================================================================
// small PTX helpers (all legal on compute_103 / sm_80+)
// ============================================================================
__device__ __forceinline__ uint32_t smem_u32(const void* p) {
    uint32_t a;
    asm("{ .reg .u64 t; cvta.to.shared.u64 t, %1; cvt.u32.u64 %0, t; }"
        : "=r"(a) : "l"(p));
    return a;
}
__device__ __forceinline__ uint32_t lds32(uint32_t a) {
    uint32_t v;
    asm volatile("ld.shared.b32 %0, [%1];" : "=r"(v) : "r"(a));
    return v;
}
__device__ __forceinline__ void sts64(uint32_t a, uint32_t x, uint32_t y) {
    asm volatile("st.shared.v2.b32 [%0], {%1, %2};" :: "r"(a), "r"(x), "r"(y) : "memory");
}
#define CP_ASYNC_16(saddr, gptr) \
    asm volatile("cp.async.cg.shared.global [%0], [%1], 16;" \
                 :: "r"(saddr), "l"(gptr) : "memory")
#define CP_ASYNC_COMMIT() asm volatile("cp.async.commit_group;" ::: "memory")
#define CP_ASYNC_WAIT0()  asm volatile("cp.async.wait_group 0;" ::: "memory")

// bf16 MMA: D(16x8,f32) += A(16x16,bf16,row) * B(16x8,bf16,col)
__device__ __forceinline__ void mma16816(float* c, const uint32_t* a, const uint32_t* b) {
    asm volatile(
        "mma.sync.aligned.m16n8k16.row.col.f32.bf16.bf16.f32 "
        "{%0,%1,%2,%3}, {%4,%5,%6,%7}, {%8,%9}, {%0,%1,%2,%3};"
        : "+f"(c[0]), "+f"(c[1]), "+f"(c[2]), "+f"(c[3])
        : "r"(a[0]), "r"(a[1]), "r"(a[2]), "r"(a[3]), "r"(b[0]), "r"(b[1]));
}

// ---------------------------------------------------------------------------
// Kernel 1: init scratch. Cols [0,512) = 0 (atomic targets), cols [512,768) = h.
// ---------------------------------------------------------------------------
__global__ void init_xcat_kernel(const float* __restrict__ h, int nAtoms) {
    size_t gid = (size_t)blockIdx.x * blockDim.x + threadIdx.x;
    size_t total = (size_t)nAtoms * (D_CAT / 4);
    if (gid >= total) return;
    int row = (int)(gid / (D_CAT / 4));
    int cv  = (int)(gid % (D_CAT / 4));
    float4 v;
    if (cv < 128) {
        v = make_float4(0.f, 0.f, 0.f, 0.f);
    } else {
        v = *(const float4*)(h + (size_t)row * D_ATOM + (size_t)(cv - 128) * 4);
    }
    *(float4*)(g_xcat + (size_t)row * D_CAT + (size_t)cv * 4) = v;
}

// ---------------------------------------------------------------------------
// Kernel 2: scatter (unchanged, validated).
// ---------------------------------------------------------------------------
__device__ __forceinline__ void red_add_v4(float* addr, float4 v) {
    asm volatile("red.global.add.v4.f32 [%0], {%1, %2, %3, %4};"
                 :: "l"(addr), "f"(v.x), "f"(v.y), "f"(v.z), "f"(v.w)
                 : "memory");
}

__global__ void scatter_kernel(const float* __restrict__ m1,
                               const float* __restrict__ m2,
                               const int* __restrict__ id1,
                               const int* __restrict__ id2,
                               const int* __restrict__ id3,
                               const int* __restrict__ id4,
                               int nEdges) {
    size_t gid = (size_t)blockIdx.x * blockDim.x + threadIdx.x;
    size_t total = (size_t)nEdges * 64;
    if (gid >= total) return;
    int e = (int)(gid >> 6);
    int c = (int)(gid & 63);

    float4 v1 = *(const float4*)(m1 + (size_t)e * D_EDGE + (size_t)c * 4);
    float4 v2 = *(const float4*)(m2 + (size_t)e * D_EDGE + (size_t)c * 4);
    float4 n1 = make_float4(-v1.x, -v1.y, -v1.z, -v1.w);
    float4 n2 = make_float4(-v2.x, -v2.y, -v2.z, -v2.w);

    int i1 = __ldg(id1 + e);
    int i2 = __ldg(id2 + e);
    int i3 = __ldg(id3 + e);
    int i4 = __ldg(id4 + e);

    size_t coff = (size_t)c * 4;
    red_add_v4(g_xcat + (size_t)i1 * D_CAT + coff,          v1);
    red_add_v4(g_xcat + (size_t)i3 * D_CAT + coff,          n1);
    red_add_v4(g_xcat + (size_t)i2 * D_CAT + D_EDGE + coff, v2);
    red_add_v4(g_xcat + (size_t)i4 * D_CAT + D_EDGE + coff, n2);
}

// ---------------------------------------------------------------------------
// Kernel 3: transpose + bf16-split W.  Wt[n][k] = W[k][n] -> (hi, lo) bf16.
// ---------------------------------------------------------------------------
__global__ void prep_w_kernel(const float* __restrict__ W) {
    int gid = blockIdx.x * blockDim.x + threadIdx.x;
    if (gid >= 256 * 768) return;
    int n = gid / 768;
    int k = gid % 768;
    float w = W[(size_t)k * 256 + n];
    __nv_bfloat16 hi = __float2bfloat16_rn(w);
    __nv_bfloat16 lo = __float2bfloat16_rn(w - __bfloat162float(hi));
    g_Wt_hi[gid] = hi;
    g_Wt_lo[gid] = lo;
}

// ---------------------------------------------------------------------------
// Kernel 4: mma.sync bf16 split-3 GEMM:
//   C[M,256] = Xcat[M,768] @ W[768,256]
//   CTA: M-tile 128 x full N=256, 512 threads (16 warps, 4x4).
//   Warp tile 32(M) x 64(N). K-tiles of 32, double-buffered SMEM.
//   Per K-tile, 3 products: Ahi*Bhi, Ahi*Blo, Alo*Bhi (fp32 accum).
// ---------------------------------------------------------------------------
#define BK 32
#define ROWB 80                       // smem row stride bytes (64B data + 16 pad)
#define OFF_A_HI 0
#define OFF_A_LO 10240                // 128*80
#define OFF_B_HI 20480
#define OFF_B_LO 40960                // +256*80
#define BUF_BYTES 61440
#define GEMM_SMEM (2 * BUF_BYTES)     // 122880

__device__ __forceinline__ void split2(float a, float b, uint32_t& hi, uint32_t& lo) {
    __nv_bfloat16 ha = __float2bfloat16_rn(a);
    __nv_bfloat16 hb = __float2bfloat16_rn(b);
    __nv_bfloat16 la = __float2bfloat16_rn(a - __bfloat162float(ha));
    __nv_bfloat16 lb = __float2bfloat16_rn(b - __bfloat162float(hb));
    hi = (uint32_t)__bfloat16_as_ushort(ha) | ((uint32_t)__bfloat16_as_ushort(hb) << 16);
    lo = (uint32_t)__bfloat16_as_ushort(la) | ((uint32_t)__bfloat16_as_ushort(lb) << 16);
}

__global__ __launch_bounds__(512, 1)
void gemm_mma_kernel(float* __restrict__ C, int M) {
    extern __shared__ char smem[];
    const uint32_t sbase = smem_u32(smem);

    const int tid = threadIdx.x;
    const int wid = tid >> 5;
    const int lid = tid & 31;
    const int wm = wid >> 2;          // 0..3  (M group of 32 rows)
    const int wn = wid & 3;           // 0..3  (N group of 64 cols)
    const int g = lid >> 2;           // 0..7
    const int q = lid & 3;            // 0..3
    const int bm = blockIdx.x * 128;
    const float* A = g_xcat;

    float acc[2][8][4];
    #pragma unroll
    for (int i = 0; i < 2; i++)
        #pragma unroll
        for (int j = 0; j < 8; j++)
            #pragma unroll
            for (int r = 0; r < 4; r++) acc[i][j][r] = 0.f;

    // ---- loader index precompute ----
    // A: idx = tid + it*512 in [0,1024): m = idx>>3, f = idx&7 (float4 in row)
    // B: idx = tid + it*512 in [0,2048): half = idx>>10, n = (idx>>2)&255, f = idx&3
    auto issue_B = [&](uint32_t dstbuf, int k0) {
        #pragma unroll
        for (int it = 0; it < 4; it++) {
            int idx = tid + it * 512;
            int hf = idx >> 10;
            int n = (idx >> 2) & 255;
            int f = idx & 3;
            const __nv_bfloat16* src = (hf ? g_Wt_lo : g_Wt_hi) + (size_t)n * D_CAT + k0 + f * 8;
            uint32_t dst = dstbuf + (hf ? OFF_B_LO : OFF_B_HI) + n * ROWB + f * 16;
            CP_ASYNC_16(dst, src);
        }
    };
    auto ldg_A = [&](float4* av, int k0) {
        #pragma unroll
        for (int it = 0; it < 2; it++) {
            int idx = tid + it * 512;
            int m = idx >> 3;
            int f = idx & 7;
            int gm = bm + m;
            av[it] = (gm < M) ? *(const float4*)(A + (size_t)gm * D_CAT + k0 + f * 4)
                              : make_float4(0.f, 0.f, 0.f, 0.f);
        }
    };
    auto sts_A = [&](uint32_t dstbuf, const float4* av) {
        #pragma unroll
        for (int it = 0; it < 2; it++) {
            int idx = tid + it * 512;
            int m = idx >> 3;
            int f = idx & 7;
            uint32_t h0, l0, h1, l1;
            split2(av[it].x, av[it].y, h0, l0);
            split2(av[it].z, av[it].w, h1, l1);
            uint32_t off = m * ROWB + f * 8;
            sts64(dstbuf + OFF_A_HI + off, h0, h1);
            sts64(dstbuf + OFF_A_LO + off, l0, l1);
        }
    };

    // ---- prologue: tile 0 ----
    {
        float4 av[2];
        issue_B(sbase, 0);
        CP_ASYNC_COMMIT();
        ldg_A(av, 0);
        sts_A(sbase, av);
        CP_ASYNC_WAIT0();
        __syncthreads();
    }

    const int NT = D_CAT / BK;   // 24
    for (int t = 0; t < NT; t++) {
        const uint32_t sb  = sbase + (t & 1) * BUF_BYTES;
        const uint32_t nxt = sbase + ((t + 1) & 1) * BUF_BYTES;
        const bool has_next = (t + 1 < NT);

        float4 av[2];
        if (has_next) {
            issue_B(nxt, (t + 1) * BK);
            CP_ASYNC_COMMIT();
            ldg_A(av, (t + 1) * BK);
        }

        // ---- compute tile t ----
        #pragma unroll
        for (int ks = 0; ks < 2; ks++) {
            uint32_t ahi[2][4], alo[2][4];
            #pragma unroll
            for (int i = 0; i < 2; i++) {
                uint32_t base = sb + (uint32_t)((wm * 32 + i * 16 + g) * ROWB + ks * 32 + q * 4);
                ahi[i][0] = lds32(base + OFF_A_HI);
                ahi[i][1] = lds32(base + OFF_A_HI + 8 * ROWB);
                ahi[i][2] = lds32(base + OFF_A_HI + 16);
                ahi[i][3] = lds32(base + OFF_A_HI + 8 * ROWB + 16);
                alo[i][0] = lds32(base + OFF_A_LO);
                alo[i][1] = lds32(base + OFF_A_LO + 8 * ROWB);
                alo[i][2] = lds32(base + OFF_A_LO + 16);
                alo[i][3] = lds32(base + OFF_A_LO + 8 * ROWB + 16);
            }
            #pragma unroll
            for (int j = 0; j < 8; j++) {
                uint32_t bb = sb + (uint32_t)((wn * 64 + j * 8 + g) * ROWB + ks * 32 + q * 4);
                uint32_t bhi[2], blo[2];
                bhi[0] = lds32(bb + OFF_B_HI);
                bhi[1] = lds32(bb + OFF_B_HI + 16);
                blo[0] = lds32(bb + OFF_B_LO);
                blo[1] = lds32(bb + OFF_B_LO + 16);
                #pragma unroll
                for (int i = 0; i < 2; i++) {
                    mma16816(acc[i][j], ahi[i], bhi);
                    mma16816(acc[i][j], ahi[i], blo);
                    mma16816(acc[i][j], alo[i], bhi);
                }
            }
        }

        if (has_next) {
            sts_A(nxt, av);
            CP_ASYNC_WAIT0();
        }
        __syncthreads();
    }

    // ---- epilogue: write accumulators ----
    #pragma unroll
    for (int i = 0; i < 2; i++) {
        int row0 = bm + wm * 32 + i * 16 + g;
        int row1 = row0 + 8;
        #pragma unroll
        for (int j = 0; j < 8; j++) {
            int col = wn * 64 + j * 8 + 2 * q;
            if (row0 < M)
                *(float2*)(C + (size_t)row0 * 256 + col) = make_float2(acc[i][j][0], acc[i][j][1]);
            if (row1 < M)
                *(float2*)(C + (size_t)row1 * 256 + col) = make_float2(acc[i][j][2], acc[i][j][3]);
        }
    }
}

// ---------------------------------------------------------------------------
// Launch. Input order (metadata): h, m1, m2, id1, id2, id3, id4, W
// ---------------------------------------------------------------------------
extern "C" void kernel_launch(void* const* d_in, const int* in_sizes, int n_in,
                              void* d_out, int out_size) {
    const float* h  = (const float*)d_in[0];
    const float* m1 = (const float*)d_in[1];
    const float* m2 = (const float*)d_in[2];
    const int* id1  = (const int*)d_in[3];
    const int* id2  = (const int*)d_in[4];
    const int* id3  = (const int*)d_in[5];
    const int* id4  = (const int*)d_in[6];
    const float* W  = (const float*)d_in[7];
    float* out      = (float*)d_out;

    const int nAtoms = in_sizes[0] / D_ATOM;   // 100000
    const int nEdges = in_sizes[3];            // 800000

    // 1) init scratch: zero x-region, copy h into concat tail
    {
        size_t total = (size_t)nAtoms * (D_CAT / 4);
        int threads = 256;
        int blocks = (int)((total + threads - 1) / threads);
        init_xcat_kernel<<<blocks, threads>>>(h, nAtoms);
    }
    // 1b) W transpose + bf16 split
    {
        int total = 256 * 768;
        prep_w_kernel<<<(total + 255) / 256, 256>>>(W);
    }
    // 2) scatter edges
    {
        size_t total = (size_t)nEdges * 64;
        int threads = 256;
        int blocks = (int)((total + threads - 1) / threads);
        scatter_kernel<<<blocks, threads>>>(m1, m2, id1, id2, id3, id4, nEdges);
    }
    // 3) tensor-core GEMM (mma.sync bf16 split-3)
    {
        cudaFuncSetAttribute(gemm_mma_kernel,
                             cudaFuncAttributeMaxDynamicSharedMemorySize,
                             GEMM_SMEM);
        int grid = (nAtoms + 127) / 128;   // 782
        gemm_mma_kernel<<<grid, 512, GEMM_SMEM>>>(out, nAtoms);
    }
}